// round 1
// baseline (speedup 1.0000x reference)
#include <cuda_runtime.h>
#include <math.h>

#define S_LEN  4096
#define DMODEL 512
#define FFDIM  2048
#define NHEAD  8
#define DHEAD  64

// ---------------- scratch (allocation-free: __device__ globals) ----------------
__device__ float g_Q[NHEAD * S_LEN * DHEAD];    // [h][s][dh]
__device__ float g_K[NHEAD * S_LEN * DHEAD];
__device__ float g_V[NHEAD * S_LEN * DHEAD];
__device__ float g_ATT[S_LEN * DMODEL];         // [s][d]
__device__ float g_T1[S_LEN * DMODEL];          // pre-LN buffers (reused)
__device__ float g_X1[S_LEN * DMODEL];          // post-LN1
__device__ float g_FF1[S_LEN * FFDIM];          // FFN hidden

enum { MODE_QKV = 0, MODE_RES = 1, MODE_RELU = 2 };

// ---------------- generic SGEMM: C = A[M,K] * W[K,N] + bias (+epilogue) --------
// BM=BN=128, BK=16, 256 threads, 8x8 per thread.
__global__ __launch_bounds__(256) void sgemm_kernel(
    const float* __restrict__ A, const float* __restrict__ W,
    const float* __restrict__ bias, const float* __restrict__ res,
    float* __restrict__ C, int M, int N, int K, int mode)
{
    __shared__ float As[16][128];   // [k][m] (transposed on load)
    __shared__ float Bs[16][128];   // [k][n]

    const int tid = threadIdx.x;
    const int tx = tid & 15;        // n-group
    const int ty = tid >> 4;        // m-group
    const int m0 = blockIdx.y << 7;
    const int n0 = blockIdx.x << 7;

    float acc[8][8];
#pragma unroll
    for (int i = 0; i < 8; ++i)
#pragma unroll
        for (int j = 0; j < 8; ++j) acc[i][j] = 0.f;

    for (int kk = 0; kk < K; kk += 16) {
        // A tile: 128 rows x 16 cols -> As transposed
#pragma unroll
        for (int f = tid; f < 512; f += 256) {
            int row = f >> 2, c4 = (f & 3) << 2;
            float4 v = *(const float4*)(A + (m0 + row) * K + kk + c4);
            As[c4 + 0][row] = v.x;
            As[c4 + 1][row] = v.y;
            As[c4 + 2][row] = v.z;
            As[c4 + 3][row] = v.w;
        }
        // B tile: 16 rows x 128 cols -> natural
#pragma unroll
        for (int f = tid; f < 512; f += 256) {
            int row = f >> 5, c4 = (f & 31) << 2;
            *(float4*)&Bs[row][c4] = *(const float4*)(W + (kk + row) * N + n0 + c4);
        }
        __syncthreads();
#pragma unroll
        for (int k = 0; k < 16; ++k) {
            float ra[8], rb[8];
            *(float4*)(ra + 0) = *(const float4*)&As[k][ty * 8 + 0];
            *(float4*)(ra + 4) = *(const float4*)&As[k][ty * 8 + 4];
            *(float4*)(rb + 0) = *(const float4*)&Bs[k][tx * 8 + 0];
            *(float4*)(rb + 4) = *(const float4*)&Bs[k][tx * 8 + 4];
#pragma unroll
            for (int i = 0; i < 8; ++i)
#pragma unroll
                for (int j = 0; j < 8; ++j) acc[i][j] += ra[i] * rb[j];
        }
        __syncthreads();
    }

    // epilogue
#pragma unroll
    for (int i = 0; i < 8; ++i) {
        const int r = m0 + ty * 8 + i;
#pragma unroll
        for (int j = 0; j < 8; ++j) {
            const int c = n0 + tx * 8 + j;
            float v = acc[i][j] + bias[c];
            if (mode == MODE_RELU) {
                v = fmaxf(v, 0.f);
                C[r * N + c] = v;
            } else if (mode == MODE_RES) {
                C[r * N + c] = v + res[r * N + c];
            } else { // MODE_QKV: scatter into [head][s][dh]
                C[((c >> 6) * M + r) * 64 + (c & 63)] = v;
            }
        }
    }
}

// ---------------- fused attention (flash-style, one head x 64 q-rows / block) --
// grid (S/64, H), 256 threads. smem exactly 48KB.
__global__ __launch_bounds__(256) void attn_kernel(const int* __restrict__ mask)
{
    __shared__ float Qst[64][64];     // [k][r]  Q transposed
    __shared__ float KVs[64 * 64];    // K transposed [k][t], later V natural [t][d]
    __shared__ float Ps[64][64];      // scores / probabilities [r][c]

    const int tid = threadIdx.x;
    const int h  = blockIdx.y;
    const int s0 = blockIdx.x << 6;

    const float* Qg = g_Q + (h * S_LEN + s0) * DHEAD;
    const float* Kg = g_K + h * S_LEN * DHEAD;
    const float* Vg = g_V + h * S_LEN * DHEAD;

    const int tx = tid & 15;          // S-compute: 4 cols  | O: 4 d-dims (dg)
    const int ty = tid >> 4;          // S-compute: 4 rows  | O: 4 rows   (rg)
    const int sr = tid >> 2;          // softmax row
    const int sq = tid & 3;           // softmax quarter (16 cols)

    // load Q transposed (once)
#pragma unroll
    for (int f = tid; f < 1024; f += 256) {
        int r = f >> 4, c4 = (f & 15) << 2;
        float4 v = *(const float4*)(Qg + r * 64 + c4);
        Qst[c4 + 0][r] = v.x;
        Qst[c4 + 1][r] = v.y;
        Qst[c4 + 2][r] = v.z;
        Qst[c4 + 3][r] = v.w;
    }

    float m_r = __int_as_float(0xff800000);   // -inf
    float l_r = 0.f;
    float o[16];
#pragma unroll
    for (int i = 0; i < 16; ++i) o[i] = 0.f;

    for (int kt = 0; kt < 64; ++kt) {
        const int t0 = kt << 6;
        __syncthreads();  // KVs/Ps free from prev iter; Qst ready on first iter

        // load K tile transposed into KVs: KVs[k*64 + t]
#pragma unroll
        for (int f = tid; f < 1024; f += 256) {
            int r = f >> 4, c4 = (f & 15) << 2;
            float4 v = *(const float4*)(Kg + (t0 + r) * 64 + c4);
            KVs[(c4 + 0) * 64 + r] = v.x;
            KVs[(c4 + 1) * 64 + r] = v.y;
            KVs[(c4 + 2) * 64 + r] = v.z;
            KVs[(c4 + 3) * 64 + r] = v.w;
        }
        __syncthreads();

        // S = Q K^T (4x4 per thread)
        float acc[4][4];
#pragma unroll
        for (int i = 0; i < 4; ++i)
#pragma unroll
            for (int j = 0; j < 4; ++j) acc[i][j] = 0.f;
        for (int k = 0; k < 64; ++k) {
            float4 ra = *(const float4*)&Qst[k][ty * 4];
            float4 rb = *(const float4*)&KVs[k * 64 + tx * 4];
            acc[0][0] += ra.x * rb.x; acc[0][1] += ra.x * rb.y;
            acc[0][2] += ra.x * rb.z; acc[0][3] += ra.x * rb.w;
            acc[1][0] += ra.y * rb.x; acc[1][1] += ra.y * rb.y;
            acc[1][2] += ra.y * rb.z; acc[1][3] += ra.y * rb.w;
            acc[2][0] += ra.z * rb.x; acc[2][1] += ra.z * rb.y;
            acc[2][2] += ra.z * rb.z; acc[2][3] += ra.z * rb.w;
            acc[3][0] += ra.w * rb.x; acc[3][1] += ra.w * rb.y;
            acc[3][2] += ra.w * rb.z; acc[3][3] += ra.w * rb.w;
        }

        // apply mask + store scores
#pragma unroll
        for (int i = 0; i < 4; ++i) {
            int r = ty * 4 + i;
            int4 mv = *(const int4*)(mask + (s0 + r) * S_LEN + t0 + tx * 4);
            float4 v;
            v.x = mv.x ? acc[i][0] : -1e9f;
            v.y = mv.y ? acc[i][1] : -1e9f;
            v.z = mv.z ? acc[i][2] : -1e9f;
            v.w = mv.w ? acc[i][3] : -1e9f;
            *(float4*)&Ps[r][tx * 4] = v;
        }
        __syncthreads();

        // load V tile (natural) into KVs: KVs[t*64 + d]
#pragma unroll
        for (int f = tid; f < 1024; f += 256) {
            int r = f >> 4, c4 = (f & 15) << 2;
            *(float4*)&KVs[r * 64 + c4] = *(const float4*)(Vg + (t0 + r) * 64 + c4);
        }

        // online softmax on row sr, cols [sq*16, sq*16+16)
        float corr;
        {
            float p[16];
            float mx = -3e38f;
#pragma unroll
            for (int u = 0; u < 4; ++u) {
                float4 v = *(const float4*)&Ps[sr][sq * 16 + u * 4];
                p[u * 4 + 0] = v.x; p[u * 4 + 1] = v.y;
                p[u * 4 + 2] = v.z; p[u * 4 + 3] = v.w;
                mx = fmaxf(mx, fmaxf(fmaxf(v.x, v.y), fmaxf(v.z, v.w)));
            }
            mx = fmaxf(mx, __shfl_xor_sync(0xffffffffu, mx, 1));
            mx = fmaxf(mx, __shfl_xor_sync(0xffffffffu, mx, 2));
            float mnew = fmaxf(m_r, mx);
            corr = __expf(m_r - mnew);   // m_r=-inf, mnew finite -> 0
            float ls = 0.f;
#pragma unroll
            for (int u = 0; u < 16; ++u) { p[u] = __expf(p[u] - mnew); ls += p[u]; }
#pragma unroll
            for (int u = 0; u < 4; ++u)
                *(float4*)&Ps[sr][sq * 16 + u * 4] =
                    make_float4(p[u * 4 + 0], p[u * 4 + 1], p[u * 4 + 2], p[u * 4 + 3]);
            ls += __shfl_xor_sync(0xffffffffu, ls, 1);
            ls += __shfl_xor_sync(0xffffffffu, ls, 2);
            l_r = l_r * corr + ls;
            m_r = mnew;
        }

        // rescale O accumulators (rows ty*4+i); corr lives at lane 4*(row&7)
#pragma unroll
        for (int i = 0; i < 4; ++i) {
            float ci = __shfl_sync(0xffffffffu, corr, ((ty & 1) * 4 + i) * 4);
            o[i * 4 + 0] *= ci; o[i * 4 + 1] *= ci;
            o[i * 4 + 2] *= ci; o[i * 4 + 3] *= ci;
        }
        __syncthreads();

        // O += P V  (thread: rows ty*4+i, dims tx*4+j)
        for (int c = 0; c < 64; ++c) {
            float4 vv = *(const float4*)&KVs[c * 64 + tx * 4];
#pragma unroll
            for (int i = 0; i < 4; ++i) {
                float p = Ps[ty * 4 + i][c];
                o[i * 4 + 0] += p * vv.x;
                o[i * 4 + 1] += p * vv.y;
                o[i * 4 + 2] += p * vv.z;
                o[i * 4 + 3] += p * vv.w;
            }
        }
    }

    // normalize + write [s][h*64+d]
#pragma unroll
    for (int i = 0; i < 4; ++i) {
        float li = __shfl_sync(0xffffffffu, l_r, ((ty & 1) * 4 + i) * 4);
        float inv = 1.f / li;
        int s = s0 + ty * 4 + i;
        float4 v = make_float4(o[i * 4 + 0] * inv, o[i * 4 + 1] * inv,
                               o[i * 4 + 2] * inv, o[i * 4 + 3] * inv);
        *(float4*)&g_ATT[s * DMODEL + h * DHEAD + tx * 4] = v;
    }
}

// ---------------- LayerNorm: one row (512) per block, 128 threads --------------
__global__ __launch_bounds__(128) void ln_kernel(
    const float* __restrict__ in, const float* __restrict__ g,
    const float* __restrict__ b, float* __restrict__ out)
{
    const int row = blockIdx.x;
    const int tid = threadIdx.x;
    float4 v = ((const float4*)(in + row * DMODEL))[tid];
    float s  = v.x + v.y + v.z + v.w;
    float sq = v.x * v.x + v.y * v.y + v.z * v.z + v.w * v.w;
#pragma unroll
    for (int off = 16; off > 0; off >>= 1) {
        s  += __shfl_xor_sync(0xffffffffu, s, off);
        sq += __shfl_xor_sync(0xffffffffu, sq, off);
    }
    __shared__ float ss[4], ssq[4];
    if ((tid & 31) == 0) { ss[tid >> 5] = s; ssq[tid >> 5] = sq; }
    __syncthreads();
    s  = ss[0] + ss[1] + ss[2] + ss[3];
    sq = ssq[0] + ssq[1] + ssq[2] + ssq[3];
    const float mean = s * (1.f / (float)DMODEL);
    const float var  = sq * (1.f / (float)DMODEL) - mean * mean;
    const float inv  = rsqrtf(var + 1e-5f);
    float4 gg = ((const float4*)g)[tid];
    float4 bb = ((const float4*)b)[tid];
    float4 r;
    r.x = (v.x - mean) * inv * gg.x + bb.x;
    r.y = (v.y - mean) * inv * gg.y + bb.y;
    r.z = (v.z - mean) * inv * gg.z + bb.z;
    r.w = (v.w - mean) * inv * gg.w + bb.w;
    ((float4*)(out + row * DMODEL))[tid] = r;
}

// ---------------- launch --------------------------------------------------------
extern "C" void kernel_launch(void* const* d_in, const int* in_sizes, int n_in,
                              void* d_out, int out_size)
{
    const float* x    = (const float*)d_in[0];
    const int*   mask = (const int*)  d_in[1];
    const float* wq = (const float*)d_in[2];
    const float* bq = (const float*)d_in[3];
    const float* wk = (const float*)d_in[4];
    const float* bk = (const float*)d_in[5];
    const float* wv = (const float*)d_in[6];
    const float* bv = (const float*)d_in[7];
    const float* wo = (const float*)d_in[8];
    const float* bo = (const float*)d_in[9];
    const float* w1 = (const float*)d_in[10];
    const float* b1 = (const float*)d_in[11];
    const float* w2 = (const float*)d_in[12];
    const float* b2 = (const float*)d_in[13];
    const float* g1  = (const float*)d_in[14];
    const float* be1 = (const float*)d_in[15];
    const float* g2  = (const float*)d_in[16];
    const float* be2 = (const float*)d_in[17];

    float *Q, *K, *V, *ATT, *T1, *X1, *FF1;
    cudaGetSymbolAddress((void**)&Q,   g_Q);
    cudaGetSymbolAddress((void**)&K,   g_K);
    cudaGetSymbolAddress((void**)&V,   g_V);
    cudaGetSymbolAddress((void**)&ATT, g_ATT);
    cudaGetSymbolAddress((void**)&T1,  g_T1);
    cudaGetSymbolAddress((void**)&X1,  g_X1);
    cudaGetSymbolAddress((void**)&FF1, g_FF1);

    dim3 blk(256);
    dim3 gD(DMODEL / 128, S_LEN / 128);   // (4, 32)
    dim3 gF(FFDIM  / 128, S_LEN / 128);   // (16, 32)

    // QKV projections (fused head-split layout in epilogue)
    sgemm_kernel<<<gD, blk>>>(x, wq, bq, nullptr, Q, S_LEN, DMODEL, DMODEL, MODE_QKV);
    sgemm_kernel<<<gD, blk>>>(x, wk, bk, nullptr, K, S_LEN, DMODEL, DMODEL, MODE_QKV);
    sgemm_kernel<<<gD, blk>>>(x, wv, bv, nullptr, V, S_LEN, DMODEL, DMODEL, MODE_QKV);

    // fused attention
    attn_kernel<<<dim3(S_LEN / 64, NHEAD), blk>>>(mask);

    // output projection + residual, LN1
    sgemm_kernel<<<gD, blk>>>(ATT, wo, bo, x, T1, S_LEN, DMODEL, DMODEL, MODE_RES);
    ln_kernel<<<S_LEN, 128>>>(T1, g1, be1, X1);

    // FFN
    sgemm_kernel<<<gF, blk>>>(X1, w1, b1, nullptr, FF1, S_LEN, FFDIM, DMODEL, MODE_RELU);
    sgemm_kernel<<<gD, blk>>>(FF1, w2, b2, X1, T1, S_LEN, DMODEL, FFDIM, MODE_RES);
    ln_kernel<<<S_LEN, 128>>>(T1, g2, be2, (float*)d_out);
}